// round 1
// baseline (speedup 1.0000x reference)
#include <cuda_runtime.h>
#include <math.h>

#define BB   16
#define NP   196
#define NT   197
#define DD   768
#define NH   12
#define YY   64
#define MH   3072
#define NMASK 100
#define ALPHA 0.1f
#define BETA  0.125f
#define EPSLN 1e-5f

// ------------------------- scratch (static device memory) -------------------------
__device__ float d_patch[BB*NP*DD];
__device__ float d_tok  [BB*NP*DD];
__device__ float d_x    [BB*NT*DD];
__device__ float d_g    [BB*NT*DD];
__device__ float d_q    [BB*NT*DD];
__device__ float d_k    [BB*NT*DD];
__device__ float d_dq   [BB*NT*DD];
__device__ float d_dk   [BB*NT*DD];
__device__ float d_hid  [BB*NT*MH];
__device__ float d_P    [BB*NH*NT*NT];
__device__ float d_Wqf  [DD*DD];   // [d][j]  j = h*64+y
__device__ float d_Wqb  [DD*DD];   // [j][d]
__device__ float d_Wkf  [DD*DD];
__device__ float d_Wkb  [DD*DD];
__device__ float d_XiT  [MH*DD];   // [j][d]

// ------------------------- reductions -------------------------
__device__ __forceinline__ float bsum(float v){
    __shared__ float sh[32];
    int lane = threadIdx.x & 31, w = threadIdx.x >> 5;
    #pragma unroll
    for (int o = 16; o; o >>= 1) v += __shfl_xor_sync(0xffffffffu, v, o);
    __syncthreads();
    if (lane == 0) sh[w] = v;
    __syncthreads();
    float r = (lane < (int)(blockDim.x >> 5)) ? sh[lane] : 0.f;
    #pragma unroll
    for (int o = 16; o; o >>= 1) r += __shfl_xor_sync(0xffffffffu, r, o);
    return r;
}
__device__ __forceinline__ float bmax(float v){
    __shared__ float sh[32];
    int lane = threadIdx.x & 31, w = threadIdx.x >> 5;
    #pragma unroll
    for (int o = 16; o; o >>= 1) v = fmaxf(v, __shfl_xor_sync(0xffffffffu, v, o));
    __syncthreads();
    if (lane == 0) sh[w] = v;
    __syncthreads();
    float r = (lane < (int)(blockDim.x >> 5)) ? sh[lane] : -3.0e38f;
    #pragma unroll
    for (int o = 16; o; o >>= 1) r = fmaxf(r, __shfl_xor_sync(0xffffffffu, r, o));
    return r;
}

// ------------------------- weight pre-transposes -------------------------
__global__ __launch_bounds__(256) void prep_w_k(const float* __restrict__ Wq,
                                                const float* __restrict__ Wk){
    int idx = blockIdx.x*256 + threadIdx.x;
    if (idx >= DD*DD) return;
    int dd = idx / DD, j = idx % DD;
    int h = j >> 6, y = j & 63;
    float vq = Wq[h*(DD*YY) + dd*YY + y];
    float vk = Wk[h*(DD*YY) + dd*YY + y];
    d_Wqf[dd*DD + j] = vq;  d_Wqb[j*DD + dd] = vq;
    d_Wkf[dd*DD + j] = vk;  d_Wkb[j*DD + dd] = vk;
}
__global__ __launch_bounds__(256) void prep_xit_k(const float* __restrict__ Xi){
    int idx = blockIdx.x*256 + threadIdx.x;
    if (idx >= DD*MH) return;
    int dd = idx / MH, j = idx % MH;
    d_XiT[j*DD + dd] = Xi[idx];
}

// ------------------------- patchify / unpatchify -------------------------
__global__ __launch_bounds__(256) void patchify_k(const float* __restrict__ img){
    int idx = blockIdx.x*256 + threadIdx.x;
    if (idx >= BB*NP*DD) return;
    int e  = idx % DD;
    int n  = (idx / DD) % NP;
    int b  = idx / (DD*NP);
    int c  = e >> 8, ph = (e >> 4) & 15, pw = e & 15;
    int kh = n / 14, kw = n % 14;
    d_patch[idx] = img[((b*3 + c)*224 + kh*16 + ph)*224 + kw*16 + pw];
}
__global__ __launch_bounds__(256) void unpatchify_k(const float* __restrict__ dec,
                                                    float* __restrict__ out){
    int idx = blockIdx.x*256 + threadIdx.x;
    if (idx >= BB*3*224*224) return;
    int ww = idx % 224;
    int hh = (idx / 224) % 224;
    int c  = (idx / (224*224)) % 3;
    int b  = idx / (3*224*224);
    int kh = hh >> 4, ph = hh & 15, kw = ww >> 4, pw = ww & 15;
    int n = kh*14 + kw;
    int e = (c << 8) + (ph << 4) + pw;
    out[idx] = dec[(b*NP + n)*DD + e];
}

// ------------------------- masking + token assembly -------------------------
// Replicates jnp.nonzero(mask==1, size=100, fill_value=0) + scatter of mask_token.
__global__ __launch_bounds__(256) void assemble_k(const int* __restrict__ mask,
                                                  const float* __restrict__ cls,
                                                  const float* __restrict__ mtok,
                                                  const float* __restrict__ pos){
    int b = blockIdx.x;
    __shared__ unsigned char flag[NP];
    int tid = threadIdx.x;
    for (int i = tid; i < NP; i += 256) flag[i] = 0;
    __syncthreads();
    if (tid == 0){
        int cnt = 0;
        const int* mrow = mask + b*NP;
        for (int i = 0; i < NP; i++)
            if (mrow[i] == 1 && cnt < NMASK){ flag[i] = 1; cnt++; }
        if (cnt < NMASK) flag[0] = 1;    // fill_value=0 padding hits token 0
    }
    __syncthreads();
    float* xb = d_x + (size_t)b*NT*DD;
    for (int d = tid; d < DD; d += 256) xb[d] = cls[d] + pos[d];
    for (int n = 0; n < NP; n++){
        const float* src = flag[n] ? mtok : (d_tok + ((size_t)b*NP + n)*DD);
        for (int d = tid; d < DD; d += 256)
            xb[(1+n)*DD + d] = src[d] + pos[(1+n)*DD + d];
    }
}

// ------------------------- layernorm -------------------------
__global__ __launch_bounds__(256) void lnorm_k(const float* __restrict__ x,
                                               float* __restrict__ g,
                                               const float* __restrict__ gamma,
                                               const float* __restrict__ delta,
                                               int skipcls){
    int row = blockIdx.x;
    int srow = row;
    if (skipcls){ int b = row / NP; srow = b*NT + 1 + (row - b*NP); }
    const float* xr = x + (size_t)srow*DD;
    float* gr = g + (size_t)row*DD;
    int tid = threadIdx.x;
    float v0 = xr[tid], v1 = xr[tid+256], v2 = xr[tid+512];
    float s = bsum(v0 + v1 + v2);
    float mean = s * (1.f/768.f);
    float e0 = v0 - mean, e1 = v1 - mean, e2 = v2 - mean;
    float s2 = bsum(e0*e0 + e1*e1 + e2*e2);
    float rinv = rsqrtf(s2 * (1.f/768.f) + EPSLN);
    float gm = gamma[0];
    gr[tid]     = gm*e0*rinv + delta[tid];
    gr[tid+256] = gm*e1*rinv + delta[tid+256];
    gr[tid+512] = gm*e2*rinv + delta[tid+512];
}

// ------------------------- SGEMM 128x128x8, 8x8 micro-tile -------------------------
// C[M,N] = op(A[M,K] @ B[K,N]); A,B,C row-major. Requires K%8==0, N%4==0.
template<bool BIAS, bool RELU, bool ACC>
__global__ __launch_bounds__(256) void sgemm_k(const float* __restrict__ A,
                                               const float* __restrict__ Bm,
                                               const float* __restrict__ bias,
                                               float* __restrict__ C,
                                               int M, int N, int K,
                                               int lda, int ldb, int ldc,
                                               float scale){
    __shared__ float As[8][128];
    __shared__ float Bs[8][128];
    int tid = threadIdx.x;
    int tx = tid & 15, ty = tid >> 4;
    int m0 = blockIdx.y * 128, n0 = blockIdx.x * 128;
    float acc[8][8];
    #pragma unroll
    for (int i=0;i<8;i++)
        #pragma unroll
        for (int j=0;j<8;j++) acc[i][j] = 0.f;

    int arow = tid >> 1;          // 0..127
    int akq  = (tid & 1) * 4;     // 0 or 4
    int bk   = tid >> 5;          // 0..7
    int bn   = (tid & 31) * 4;    // 0..124

    for (int k0 = 0; k0 < K; k0 += 8){
        float4 av = make_float4(0.f,0.f,0.f,0.f);
        int gm = m0 + arow;
        if (gm < M) av = *(const float4*)(A + (size_t)gm*lda + k0 + akq);
        As[akq+0][arow] = av.x; As[akq+1][arow] = av.y;
        As[akq+2][arow] = av.z; As[akq+3][arow] = av.w;
        float4 bv = make_float4(0.f,0.f,0.f,0.f);
        if (n0 + bn < N) bv = *(const float4*)(Bm + (size_t)(k0+bk)*ldb + n0 + bn);
        *(float4*)&Bs[bk][bn] = bv;
        __syncthreads();
        #pragma unroll
        for (int kk = 0; kk < 8; kk++){
            float4 a0 = *(const float4*)&As[kk][ty*4];
            float4 a1 = *(const float4*)&As[kk][ty*4 + 64];
            float4 b0 = *(const float4*)&Bs[kk][tx*4];
            float4 b1 = *(const float4*)&Bs[kk][tx*4 + 64];
            float a[8] = {a0.x,a0.y,a0.z,a0.w,a1.x,a1.y,a1.z,a1.w};
            float b[8] = {b0.x,b0.y,b0.z,b0.w,b1.x,b1.y,b1.z,b1.w};
            #pragma unroll
            for (int i=0;i<8;i++)
                #pragma unroll
                for (int j=0;j<8;j++)
                    acc[i][j] += a[i]*b[j];
        }
        __syncthreads();
    }
    #pragma unroll
    for (int i=0;i<8;i++){
        int gm = m0 + ((i<4) ? (ty*4 + i) : (64 + ty*4 + i - 4));
        if (gm >= M) continue;
        #pragma unroll
        for (int j=0;j<8;j++){
            int gn = n0 + ((j<4) ? (tx*4 + j) : (64 + tx*4 + j - 4));
            if (gn >= N) continue;
            float v = acc[i][j];
            if (BIAS) v += bias[gn];
            if (RELU) v = fmaxf(v, 0.f);
            float* cp = C + (size_t)gm*ldc + gn;
            if (ACC) *cp += scale*v; else *cp = v;
        }
    }
}

// ------------------------- attention scores: A = BETA * Q K^T -------------------------
__global__ __launch_bounds__(256) void attn_scores_k(){
    int bh = blockIdx.z;
    int b = bh / NH, h = bh - b*NH;
    int n0 = blockIdx.y * 32, m0 = blockIdx.x * 32;
    __shared__ float Qs[32][65];
    __shared__ float Ks[32][65];
    const float* qb = d_q + (size_t)(b*NT)*DD + h*YY;
    const float* kb = d_k + (size_t)(b*NT)*DD + h*YY;
    for (int i = threadIdx.x; i < 2048; i += 256){
        int r = i >> 6, y = i & 63;
        Qs[r][y] = (n0 + r < NT) ? qb[(size_t)(n0+r)*DD + y] : 0.f;
        Ks[r][y] = (m0 + r < NT) ? kb[(size_t)(m0+r)*DD + y] : 0.f;
    }
    __syncthreads();
    for (int i = threadIdx.x; i < 1024; i += 256){
        int n = i >> 5, m = i & 31;
        float acc = 0.f;
        #pragma unroll
        for (int y = 0; y < 64; y++) acc += Qs[n][y]*Ks[m][y];
        if (n0 + n < NT && m0 + m < NT)
            d_P[((size_t)bh*NT + n0 + n)*NT + m0 + m] = BETA * acc;
    }
}

// ------------------------- row softmax over last axis (m) -------------------------
__global__ __launch_bounds__(256) void softmax_k(){
    int row = blockIdx.x;
    float* p = d_P + (size_t)row*NT;
    int tid = threadIdx.x;
    float v = (tid < NT) ? p[tid] : -3.0e38f;
    float mx = bmax(v);
    float e = (tid < NT) ? expf(v - mx) : 0.f;
    float s = bsum(e);
    if (tid < NT) p[tid] = e / s;
}

// ------------------------- O[r,y] = sum_t Ptile(r,t) * V[t,y] -------------------------
// TRANSP=false: Ptile(r,t)=P[r0+r, t] (dq = P@K).  TRANSP=true: Ptile(r,t)=P[t, r0+r] (dk = P^T@Q).
template<bool TRANSP>
__global__ __launch_bounds__(256) void pv_k(const float* __restrict__ V, float* __restrict__ O){
    int bh = blockIdx.y;
    int b = bh / NH, h = bh - b*NH;
    int r0 = blockIdx.x * 32;
    __shared__ float Ps[32][33];
    __shared__ float Vs[32][68];
    const float* Pb = d_P + (size_t)bh*NT*NT;
    const float* vb = V + (size_t)(b*NT)*DD + h*YY;
    int r  = threadIdx.x >> 3;       // 0..31
    int yb = (threadIdx.x & 7) * 8;  // 0..56
    float acc[8];
    #pragma unroll
    for (int j=0;j<8;j++) acc[j]=0.f;
    for (int t0 = 0; t0 < NT; t0 += 32){
        for (int i = threadIdx.x; i < 1024; i += 256){
            if (!TRANSP){
                int rr = i >> 5, tt = i & 31;
                Ps[rr][tt] = (r0+rr < NT && t0+tt < NT) ? Pb[(size_t)(r0+rr)*NT + t0+tt] : 0.f;
            } else {
                int tt = i >> 5, rr = i & 31;
                Ps[rr][tt] = (t0+tt < NT && r0+rr < NT) ? Pb[(size_t)(t0+tt)*NT + r0+rr] : 0.f;
            }
        }
        for (int i = threadIdx.x; i < 2048; i += 256){
            int tt = i >> 6, y = i & 63;
            Vs[tt][y] = (t0+tt < NT) ? vb[(size_t)(t0+tt)*DD + y] : 0.f;
        }
        __syncthreads();
        #pragma unroll
        for (int tt = 0; tt < 32; tt++){
            float pvv = Ps[r][tt];
            float4 v0 = *(const float4*)&Vs[tt][yb];
            float4 v1 = *(const float4*)&Vs[tt][yb+4];
            acc[0] += pvv*v0.x; acc[1] += pvv*v0.y; acc[2] += pvv*v0.z; acc[3] += pvv*v0.w;
            acc[4] += pvv*v1.x; acc[5] += pvv*v1.y; acc[6] += pvv*v1.z; acc[7] += pvv*v1.w;
        }
        __syncthreads();
    }
    if (r0 + r < NT){
        float* ob = O + ((size_t)(b*NT) + r0 + r)*DD + h*YY + yb;
        #pragma unroll
        for (int j=0;j<8;j++) ob[j] = acc[j];
    }
}

// ------------------------- host orchestration -------------------------
template<typename T>
static float* symaddr(const T& s){ void* p = nullptr; cudaGetSymbolAddress(&p, s); return (float*)p; }

extern "C" void kernel_launch(void* const* d_in, const int* in_sizes, int n_in,
                              void* d_out, int out_size){
    const float* img   = (const float*)d_in[0];
    const int*   mask  = (const int*)  d_in[1];
    const float* enc_W = (const float*)d_in[2];
    const float* enc_b = (const float*)d_in[3];
    const float* dec_W = (const float*)d_in[4];
    const float* dec_b = (const float*)d_in[5];
    const float* cls   = (const float*)d_in[6];
    const float* mtok  = (const float*)d_in[7];
    const float* pos   = (const float*)d_in[8];
    const float* Wq    = (const float*)d_in[9];
    const float* Wk    = (const float*)d_in[10];
    const float* Xi    = (const float*)d_in[11];
    const float* gamma = (const float*)d_in[12];
    const float* delta = (const float*)d_in[13];
    float* out = (float*)d_out;

    float* p_patch = symaddr(d_patch);
    float* p_tok   = symaddr(d_tok);
    float* p_x     = symaddr(d_x);
    float* p_g     = symaddr(d_g);
    float* p_q     = symaddr(d_q);
    float* p_k     = symaddr(d_k);
    float* p_dq    = symaddr(d_dq);
    float* p_dk    = symaddr(d_dk);
    float* p_hid   = symaddr(d_hid);
    float* p_wqf   = symaddr(d_Wqf);
    float* p_wqb   = symaddr(d_Wqb);
    float* p_wkf   = symaddr(d_Wkf);
    float* p_wkb   = symaddr(d_Wkb);
    float* p_xit   = symaddr(d_XiT);

    const int MROWS = BB*NT;   // 3152
    const int PROWS = BB*NP;   // 3136

    // weight pre-transposes
    prep_w_k  <<<(DD*DD + 255)/256, 256>>>(Wq, Wk);
    prep_xit_k<<<(DD*MH + 255)/256, 256>>>(Xi);

    // encode
    patchify_k<<<(BB*NP*DD + 255)/256, 256>>>(img);
    sgemm_k<true,false,false><<<dim3(6,25),256>>>(p_patch, enc_W, enc_b, p_tok,
                                                  PROWS, DD, DD, DD, DD, DD, 0.f);
    assemble_k<<<BB,256>>>(mask, cls, mtok, pos);

    // 12 energy-descent steps
    for (int it = 0; it < 12; it++){
        lnorm_k<<<MROWS,256>>>(p_x, p_g, gamma, delta, 0);
        sgemm_k<false,false,false><<<dim3(6,25),256>>>(p_g, p_wqf, nullptr, p_q,
                                                       MROWS, DD, DD, DD, DD, DD, 0.f);
        sgemm_k<false,false,false><<<dim3(6,25),256>>>(p_g, p_wkf, nullptr, p_k,
                                                       MROWS, DD, DD, DD, DD, DD, 0.f);
        attn_scores_k<<<dim3(7,7,BB*NH),256>>>();
        softmax_k<<<BB*NH*NT,256>>>();
        pv_k<false><<<dim3(7,BB*NH),256>>>(p_k, p_dq);   // dq = P @ K
        pv_k<true ><<<dim3(7,BB*NH),256>>>(p_q, p_dk);   // dk = P^T @ Q
        // x += ALPHA * (dq @ Wq^T + dk @ Wk^T + hid @ Xi^T)
        sgemm_k<false,false,true><<<dim3(6,25),256>>>(p_dq, p_wqb, nullptr, p_x,
                                                      MROWS, DD, DD, DD, DD, DD, ALPHA);
        sgemm_k<false,false,true><<<dim3(6,25),256>>>(p_dk, p_wkb, nullptr, p_x,
                                                      MROWS, DD, DD, DD, DD, DD, ALPHA);
        sgemm_k<false,true,false><<<dim3(24,25),256>>>(p_g, Xi, nullptr, p_hid,
                                                       MROWS, MH, DD, DD, MH, MH, 0.f);
        sgemm_k<false,false,true><<<dim3(6,25),256>>>(p_hid, p_xit, nullptr, p_x,
                                                      MROWS, DD, MH, MH, DD, DD, ALPHA);
    }

    // decode (skip cls): g2 in d_patch, dec in d_tok
    lnorm_k<<<PROWS,256>>>(p_x, p_patch, gamma, delta, 1);
    sgemm_k<true,false,false><<<dim3(6,25),256>>>(p_patch, dec_W, dec_b, p_tok,
                                                  PROWS, DD, DD, DD, DD, DD, 0.f);
    unpatchify_k<<<(BB*3*224*224 + 255)/256, 256>>>(p_tok, out);
}

// round 3
// speedup vs baseline: 3.2394x; 3.2394x over previous
#include <cuda_runtime.h>
#include <cuda_bf16.h>
#include <math.h>
#include <stdint.h>

#define BB   16
#define NP   196
#define NT   197
#define DD   768
#define NH   12
#define YY   64
#define MH   3072
#define NMASK 100
#define ALPHA 0.1f
#define BETA  0.125f
#define EPSLN 1e-5f

typedef __nv_bfloat16 bf16;

// ------------------------- scratch (static device memory) -------------------------
__device__ float d_x   [BB*NT*DD];
__device__ float d_qk  [BB*NT*2*DD];       // q cols 0..767, k cols 768..1535
__device__ float d_tok [BB*NP*DD];
__device__ float d_P   [BB*NH*NT*NT];

__device__ bf16 g_hi [BB*NT*DD],      g_lo [BB*NT*DD];
__device__ bf16 hid_hi[BB*NT*MH],     hid_lo[BB*NT*MH];
__device__ bf16 dqk_hi[BB*NT*2*DD],   dqk_lo[BB*NT*2*DD];
__device__ bf16 pat_hi[BB*NP*DD],     pat_lo[BB*NP*DD];

__device__ bf16 w_encT_hi[DD*DD],     w_encT_lo[DD*DD];     // [N=768,K=768]
__device__ bf16 w_decT_hi[DD*DD],     w_decT_lo[DD*DD];
__device__ bf16 w_qkfT_hi[2*DD*DD],   w_qkfT_lo[2*DD*DD];   // [1536,768]
__device__ bf16 w_qkbT_hi[2*DD*DD],   w_qkbT_lo[2*DD*DD];   // [768,1536]
__device__ bf16 w_xiT_hi [MH*DD],     w_xiT_lo [MH*DD];     // [3072,768]
__device__ bf16 w_xi_hi  [DD*MH],     w_xi_lo  [DD*MH];     // [768,3072]

// ------------------------- helpers -------------------------
__device__ __forceinline__ void split2(float v, bf16& h, bf16& l){
    h = __float2bfloat16(v);
    l = __float2bfloat16(v - __bfloat162float(h));
}

__device__ __forceinline__ void cp16(uint32_t saddr, const bf16* g, uint32_t sz){
    uint64_t ga = __cvta_generic_to_global(g);
    asm volatile("cp.async.cg.shared.global [%0], [%1], 16, %2;"
                 :: "r"(saddr), "l"(ga), "r"(sz) : "memory");
}
__device__ __forceinline__ void cp_commit(){ asm volatile("cp.async.commit_group;" ::: "memory"); }
template<int N>
__device__ __forceinline__ void cp_wait(){ asm volatile("cp.async.wait_group %0;" :: "n"(N) : "memory"); }

__device__ __forceinline__ void ldsm4(uint32_t* r, uint32_t a){
    asm volatile("ldmatrix.sync.aligned.m8n8.x4.shared.b16 {%0,%1,%2,%3}, [%4];"
                 : "=r"(r[0]), "=r"(r[1]), "=r"(r[2]), "=r"(r[3]) : "r"(a));
}
__device__ __forceinline__ void ldsm2(uint32_t* r, uint32_t a){
    asm volatile("ldmatrix.sync.aligned.m8n8.x2.shared.b16 {%0,%1}, [%2];"
                 : "=r"(r[0]), "=r"(r[1]) : "r"(a));
}
__device__ __forceinline__ void mma16816(float* c, const uint32_t* a, const uint32_t* b){
    asm volatile("mma.sync.aligned.m16n8k16.row.col.f32.bf16.bf16.f32 "
                 "{%0,%1,%2,%3}, {%4,%5,%6,%7}, {%8,%9}, {%0,%1,%2,%3};"
                 : "+f"(c[0]), "+f"(c[1]), "+f"(c[2]), "+f"(c[3])
                 : "r"(a[0]), "r"(a[1]), "r"(a[2]), "r"(a[3]), "r"(b[0]), "r"(b[1]));
}

// ------------------------- reductions -------------------------
__device__ __forceinline__ float bsum(float v){
    __shared__ float sh[32];
    int lane = threadIdx.x & 31, w = threadIdx.x >> 5;
    #pragma unroll
    for (int o = 16; o; o >>= 1) v += __shfl_xor_sync(0xffffffffu, v, o);
    __syncthreads();
    if (lane == 0) sh[w] = v;
    __syncthreads();
    float r = (lane < (int)(blockDim.x >> 5)) ? sh[lane] : 0.f;
    #pragma unroll
    for (int o = 16; o; o >>= 1) r += __shfl_xor_sync(0xffffffffu, r, o);
    return r;
}
__device__ __forceinline__ float bmax(float v){
    __shared__ float sh[32];
    int lane = threadIdx.x & 31, w = threadIdx.x >> 5;
    #pragma unroll
    for (int o = 16; o; o >>= 1) v = fmaxf(v, __shfl_xor_sync(0xffffffffu, v, o));
    __syncthreads();
    if (lane == 0) sh[w] = v;
    __syncthreads();
    float r = (lane < (int)(blockDim.x >> 5)) ? sh[lane] : -3.0e38f;
    #pragma unroll
    for (int o = 16; o; o >>= 1) r = fmaxf(r, __shfl_xor_sync(0xffffffffu, r, o));
    return r;
}

// ------------------------- weight prep -------------------------
__global__ __launch_bounds__(256) void split_transpose_k(const float* __restrict__ W,
                                                         bf16* __restrict__ hi,
                                                         bf16* __restrict__ lo,
                                                         int R, int C){
    int o = blockIdx.x*256 + threadIdx.x;
    if (o >= R*C) return;
    int c = o / R, r = o - c*R;
    bf16 h, l; split2(W[(size_t)r*C + c], h, l);
    hi[o] = h; lo[o] = l;
}
__global__ __launch_bounds__(256) void split_k(const float* __restrict__ W,
                                               bf16* __restrict__ hi,
                                               bf16* __restrict__ lo, int n){
    int o = blockIdx.x*256 + threadIdx.x;
    if (o >= n) return;
    bf16 h, l; split2(W[o], h, l);
    hi[o] = h; lo[o] = l;
}
__global__ __launch_bounds__(256) void prep_qk_k(const float* __restrict__ Wq,
                                                 const float* __restrict__ Wk){
    int o = blockIdx.x*256 + threadIdx.x;
    if (o >= 2*DD*DD) return;
    int j = o / DD, d = o - j*DD;
    int jj = (j < DD) ? j : j - DD;
    int h = jj >> 6, y = jj & 63;
    const float* W = (j < DD) ? Wq : Wk;
    float v = W[(size_t)h*DD*YY + (size_t)d*YY + y];
    bf16 vh, vl; split2(v, vh, vl);
    w_qkfT_hi[(size_t)j*DD + d]   = vh;  w_qkfT_lo[(size_t)j*DD + d]   = vl;
    w_qkbT_hi[(size_t)d*2*DD + j] = vh;  w_qkbT_lo[(size_t)d*2*DD + j] = vl;
}

// ------------------------- patchify / unpatchify -------------------------
__global__ __launch_bounds__(256) void patchify_k(const float* __restrict__ img){
    int idx = blockIdx.x*256 + threadIdx.x;
    if (idx >= BB*NP*DD) return;
    int e  = idx % DD;
    int n  = (idx / DD) % NP;
    int b  = idx / (DD*NP);
    int c  = e >> 8, ph = (e >> 4) & 15, pw = e & 15;
    int kh = n / 14, kw = n % 14;
    float v = img[((b*3 + c)*224 + kh*16 + ph)*224 + kw*16 + pw];
    bf16 h, l; split2(v, h, l);
    pat_hi[idx] = h; pat_lo[idx] = l;
}
__global__ __launch_bounds__(256) void unpatchify_k(const float* __restrict__ dec,
                                                    float* __restrict__ out){
    int idx = blockIdx.x*256 + threadIdx.x;
    if (idx >= BB*3*224*224) return;
    int ww = idx % 224;
    int hh = (idx / 224) % 224;
    int c  = (idx / (224*224)) % 3;
    int b  = idx / (3*224*224);
    int kh = hh >> 4, ph = hh & 15, kw = ww >> 4, pw = ww & 15;
    int n = kh*14 + kw;
    int e = (c << 8) + (ph << 4) + pw;
    out[idx] = dec[(size_t)(b*NP + n)*DD + e];
}

// ------------------------- masking + token assembly -------------------------
__global__ __launch_bounds__(256) void assemble_k(const int* __restrict__ mask,
                                                  const float* __restrict__ cls,
                                                  const float* __restrict__ mtok,
                                                  const float* __restrict__ pos){
    int b = blockIdx.x;
    __shared__ unsigned char flag[NP];
    int tid = threadIdx.x;
    for (int i = tid; i < NP; i += 256) flag[i] = 0;
    __syncthreads();
    if (tid == 0){
        int cnt = 0;
        const int* mrow = mask + b*NP;
        for (int i = 0; i < NP; i++)
            if (mrow[i] == 1 && cnt < NMASK){ flag[i] = 1; cnt++; }
        if (cnt < NMASK) flag[0] = 1;
    }
    __syncthreads();
    float* xb = d_x + (size_t)b*NT*DD;
    for (int d = tid; d < DD; d += 256) xb[d] = cls[d] + pos[d];
    for (int n = 0; n < NP; n++){
        const float* src = flag[n] ? mtok : (d_tok + ((size_t)b*NP + n)*DD);
        for (int d = tid; d < DD; d += 256)
            xb[(1+n)*DD + d] = src[d] + pos[(1+n)*DD + d];
    }
}

// ------------------------- layernorm (emits bf16 hi/lo) -------------------------
__global__ __launch_bounds__(256) void lnorm_k(const float* __restrict__ x,
                                               bf16* __restrict__ ghi,
                                               bf16* __restrict__ glo,
                                               const float* __restrict__ gamma,
                                               const float* __restrict__ delta,
                                               int skipcls){
    int row = blockIdx.x;
    int srow = row;
    if (skipcls){ int b = row / NP; srow = b*NT + 1 + (row - b*NP); }
    const float* xr = x + (size_t)srow*DD;
    int tid = threadIdx.x;
    float v0 = xr[tid], v1 = xr[tid+256], v2 = xr[tid+512];
    float s = bsum(v0 + v1 + v2);
    float mean = s * (1.f/768.f);
    float e0 = v0 - mean, e1 = v1 - mean, e2 = v2 - mean;
    float s2 = bsum(e0*e0 + e1*e1 + e2*e2);
    float rinv = rsqrtf(s2 * (1.f/768.f) + EPSLN);
    float gm = gamma[0];
    float o0 = gm*e0*rinv + delta[tid];
    float o1 = gm*e1*rinv + delta[tid+256];
    float o2 = gm*e2*rinv + delta[tid+512];
    bf16* gh = ghi + (size_t)row*DD;
    bf16* gl = glo + (size_t)row*DD;
    bf16 h, l;
    split2(o0, h, l); gh[tid]     = h; gl[tid]     = l;
    split2(o1, h, l); gh[tid+256] = h; gl[tid+256] = l;
    split2(o2, h, l); gh[tid+512] = h; gl[tid+512] = l;
}

// ------------------------- mma.sync split-bf16 GEMM -------------------------
// C[M,N] = sum_k A[m,k]*B[n,k], A = Ahi+Alo, B = Bhi+Blo (3 MMA terms).
// CTA tile 128x128, 8 warps (2x4), per-warp 64x32.  K staged by 64 with
// cp.async double buffering.  Rows padded to 144B -> conflict-free ldmatrix.
// EPI: 0 = store fp32, 1 = +bias, 2 = relu + split bf16, 3 = C += ALPHA*acc
#define TILE_B   18432             // 128 rows * 144 bytes
#define STAGE_B  (4*TILE_B)        // Ahi, Alo, Bhi, Blo
#define GEMM_SMEM (2*STAGE_B)      // 147456

template<int EPI>
__global__ __launch_bounds__(256) void mma_gemm_k(
        const bf16* __restrict__ Ahi, const bf16* __restrict__ Alo,
        const bf16* __restrict__ Bhi, const bf16* __restrict__ Blo,
        const float* __restrict__ bias, float* __restrict__ C,
        bf16* __restrict__ Chi, bf16* __restrict__ Clo,
        int M, int N, int K, int lda, int ldb, int ldc){
    extern __shared__ char smem[];
    uint32_t sb = (uint32_t)__cvta_generic_to_shared(smem);
    int tid = threadIdx.x;
    int lane = tid & 31, wid = tid >> 5;
    int wm = wid >> 2, wn = wid & 3;
    int m0 = blockIdx.y * 128, n0 = blockIdx.x * 128;
    int mrows = M - m0; if (mrows > 128) mrows = 128;
    int nst = K >> 6;

    float acc[4][4][4];
    #pragma unroll
    for (int a = 0; a < 4; a++)
        #pragma unroll
        for (int b = 0; b < 4; b++)
            #pragma unroll
            for (int c = 0; c < 4; c++) acc[a][b][c] = 0.f;

    // ---- stage loader (cp.async) ----
    auto load_stage = [&](int s){
        uint32_t base = sb + (s & 1) * STAGE_B;
        int k0 = s << 6;
        #pragma unroll
        for (int it = 0; it < 4; it++){
            int c = (it << 8) + tid;        // 0..1023
            int r = c >> 3;                 // 0..127
            int kq = (c & 7) << 3;          // 0..56
            uint32_t soff = r*144 + (kq << 1);
            uint32_t szA = (r < mrows) ? 16u : 0u;
            int ra = (r < mrows) ? r : 0;
            cp16(base + soff,            Ahi + (size_t)(m0+ra)*lda + k0 + kq, szA);
            cp16(base + TILE_B + soff,   Alo + (size_t)(m0+ra)*lda + k0 + kq, szA);
            cp16(base + 2*TILE_B + soff, Bhi + (size_t)(n0+r)*ldb + k0 + kq, 16u);
            cp16(base + 3*TILE_B + soff, Blo + (size_t)(n0+r)*ldb + k0 + kq, 16u);
        }
        cp_commit();
    };

    auto compute_stage = [&](int s){
        uint32_t base = sb + (s & 1) * STAGE_B;
        uint32_t aRow = (uint32_t)(wm*64 + (lane & 15))*144;
        uint32_t aHi8 = (uint32_t)((lane >> 4) << 3);
        uint32_t bRow = (uint32_t)(wn*32 + (lane & 7))*144;
        uint32_t bHi8 = (uint32_t)(((lane >> 3) & 1) << 3);
        #pragma unroll
        for (int kk = 0; kk < 64; kk += 16){
            uint32_t ah[4][4], al[4][4], bh[4][2], bl[4][2];
            uint32_t aoff = base + aRow + ((kk + aHi8) << 1);
            uint32_t boff = base + 2*TILE_B + bRow + ((kk + bHi8) << 1);
            #pragma unroll
            for (int mt = 0; mt < 4; mt++){
                ldsm4(ah[mt], aoff + mt*(16*144));
                ldsm4(al[mt], aoff + TILE_B + mt*(16*144));
            }
            #pragma unroll
            for (int nt = 0; nt < 4; nt++){
                ldsm2(bh[nt], boff + nt*(8*144));
                ldsm2(bl[nt], boff + TILE_B + nt*(8*144));
            }
            #pragma unroll
            for (int mt = 0; mt < 4; mt++)
                #pragma unroll
                for (int nt = 0; nt < 4; nt++){
                    mma16816(acc[mt][nt], ah[mt], bh[nt]);
                    mma16816(acc[mt][nt], ah[mt], bl[nt]);
                    mma16816(acc[mt][nt], al[mt], bh[nt]);
                }
        }
    };

    load_stage(0);
    for (int s = 0; s < nst; s++){
        if (s + 1 < nst){
            load_stage(s + 1);
            cp_wait<1>();
        } else {
            cp_wait<0>();
        }
        __syncthreads();
        compute_stage(s);
        __syncthreads();
    }

    // ---- epilogue ----
    int g = lane >> 2;
    int t2 = (lane & 3) << 1;
    #pragma unroll
    for (int mt = 0; mt < 4; mt++){
        int r0 = m0 + wm*64 + mt*16 + g;
        #pragma unroll
        for (int half = 0; half < 2; half++){
            int row = r0 + half*8;
            if (row >= M) continue;
            #pragma unroll
            for (int nt = 0; nt < 4; nt++){
                int col = n0 + wn*32 + nt*8 + t2;
                float v0 = acc[mt][nt][half*2];
                float v1 = acc[mt][nt][half*2 + 1];
                if (EPI == 0 || EPI == 1){
                    if (EPI == 1){ v0 += bias[col]; v1 += bias[col+1]; }
                    float2* cp = (float2*)(C + (size_t)row*ldc + col);
                    *cp = make_float2(v0, v1);
                } else if (EPI == 2){
                    v0 = fmaxf(v0, 0.f); v1 = fmaxf(v1, 0.f);
                    bf16 h0, l0, h1, l1;
                    split2(v0, h0, l0); split2(v1, h1, l1);
                    *(__nv_bfloat162*)(Chi + (size_t)row*ldc + col) = __halves2bfloat162(h0, h1);
                    *(__nv_bfloat162*)(Clo + (size_t)row*ldc + col) = __halves2bfloat162(l0, l1);
                } else {
                    float2* cp = (float2*)(C + (size_t)row*ldc + col);
                    float2 o = *cp;
                    o.x += ALPHA * v0;
                    o.y += ALPHA * v1;
                    *cp = o;
                }
            }
        }
    }
}

// ------------------------- attention scores: A = BETA * Q K^T -------------------------
__global__ __launch_bounds__(256) void attn_scores_k(){
    int bh = blockIdx.z;
    int b = bh / NH, h = bh - b*NH;
    int n0 = blockIdx.y * 32, m0 = blockIdx.x * 32;
    __shared__ float Qs[32][65];
    __shared__ float Ks[32][65];
    const float* qb = d_qk + (size_t)(b*NT)*(2*DD) + h*YY;
    const float* kb = qb + DD;
    for (int i = threadIdx.x; i < 2048; i += 256){
        int r = i >> 6, y = i & 63;
        Qs[r][y] = (n0 + r < NT) ? qb[(size_t)(n0+r)*(2*DD) + y] : 0.f;
        Ks[r][y] = (m0 + r < NT) ? kb[(size_t)(m0+r)*(2*DD) + y] : 0.f;
    }
    __syncthreads();
    for (int i = threadIdx.x; i < 1024; i += 256){
        int n = i >> 5, m = i & 31;
        float acc = 0.f;
        #pragma unroll
        for (int y = 0; y < 64; y++) acc += Qs[n][y]*Ks[m][y];
        if (n0 + n < NT && m0 + m < NT)
            d_P[((size_t)bh*NT + n0 + n)*NT + m0 + m] = BETA * acc;
    }
}

// ------------------------- row softmax -------------------------
__global__ __launch_bounds__(256) void softmax_k(){
    int row = blockIdx.x;
    float* p = d_P + (size_t)row*NT;
    int tid = threadIdx.x;
    float v = (tid < NT) ? p[tid] : -3.0e38f;
    float mx = bmax(v);
    float e = (tid < NT) ? expf(v - mx) : 0.f;
    float s = bsum(e);
    if (tid < NT) p[tid] = e / s;
}

// ------------------------- PV: writes split bf16 into fused dqdk -------------------------
template<bool TRANSP>
__global__ __launch_bounds__(256) void pv_k(){
    int bh = blockIdx.y;
    int b = bh / NH, h = bh - b*NH;
    int r0 = blockIdx.x * 32;
    __shared__ float Ps[32][33];
    __shared__ float Vs[32][68];
    const float* Pb = d_P + (size_t)bh*NT*NT;
    const float* vb = d_qk + (size_t)(b*NT)*(2*DD) + (TRANSP ? 0 : DD) + h*YY;
    int r  = threadIdx.x >> 3;
    int yb = (threadIdx.x & 7) * 8;
    float acc[8];
    #pragma unroll
    for (int j = 0; j < 8; j++) acc[j] = 0.f;
    for (int t0 = 0; t0 < NT; t0 += 32){
        for (int i = threadIdx.x; i < 1024; i += 256){
            if (!TRANSP){
                int rr = i >> 5, tt = i & 31;
                Ps[rr][tt] = (r0+rr < NT && t0+tt < NT) ? Pb[(size_t)(r0+rr)*NT + t0+tt] : 0.f;
            } else {
                int tt = i >> 5, rr = i & 31;
                Ps[rr][tt] = (t0+tt < NT && r0+rr < NT) ? Pb[(size_t)(t0+tt)*NT + r0+rr] : 0.f;
            }
        }
        for (int i = threadIdx.x; i < 2048; i += 256){
            int tt = i >> 6, y = i & 63;
            Vs[tt][y] = (t0+tt < NT) ? vb[(size_t)(t0+tt)*(2*DD) + y] : 0.f;
        }
        __syncthreads();
        #pragma unroll
        for (int tt = 0; tt < 32; tt++){
            float pvv = Ps[r][tt];
            float4 v0 = *(const float4*)&Vs[tt][yb];
            float4 v1 = *(const float4*)&Vs[tt][yb+4];
            acc[0] += pvv*v0.x; acc[1] += pvv*v0.y; acc[2] += pvv*v0.z; acc[3] += pvv*v0.w;
            acc[4] += pvv*v1.x; acc[5] += pvv*v1.y; acc[6] += pvv*v1.z; acc[7] += pvv*v1.w;
        }
        __syncthreads();
    }
    if (r0 + r < NT){
        size_t base = ((size_t)(b*NT) + r0 + r)*(2*DD) + (TRANSP ? DD : 0) + h*YY + yb;
        #pragma unroll
        for (int j = 0; j < 8; j += 2){
            bf16 h0, l0, h1, l1;
            split2(acc[j],   h0, l0);
            split2(acc[j+1], h1, l1);
            *(__nv_bfloat162*)(dqk_hi + base + j) = __halves2bfloat162(h0, h1);
            *(__nv_bfloat162*)(dqk_lo + base + j) = __halves2bfloat162(l0, l1);
        }
    }
}

// ------------------------- host orchestration -------------------------
template<typename T>
static float* symaddrf(const T& s){ void* p = nullptr; cudaGetSymbolAddress(&p, s); return (float*)p; }
template<typename T>
static bf16* symaddrb(const T& s){ void* p = nullptr; cudaGetSymbolAddress(&p, s); return (bf16*)p; }

extern "C" void kernel_launch(void* const* d_in, const int* in_sizes, int n_in,
                              void* d_out, int out_size){
    const float* img   = (const float*)d_in[0];
    const int*   mask  = (const int*)  d_in[1];
    const float* enc_W = (const float*)d_in[2];
    const float* enc_b = (const float*)d_in[3];
    const float* dec_W = (const float*)d_in[4];
    const float* dec_b = (const float*)d_in[5];
    const float* cls   = (const float*)d_in[6];
    const float* mtok  = (const float*)d_in[7];
    const float* pos   = (const float*)d_in[8];
    const float* Wq    = (const float*)d_in[9];
    const float* Wk    = (const float*)d_in[10];
    const float* Xi    = (const float*)d_in[11];
    const float* gamma = (const float*)d_in[12];
    const float* delta = (const float*)d_in[13];
    float* out = (float*)d_out;

    float* p_x    = symaddrf(d_x);
    float* p_qk   = symaddrf(d_qk);
    float* p_tok  = symaddrf(d_tok);
    bf16* p_ghi   = symaddrb(g_hi);    bf16* p_glo   = symaddrb(g_lo);
    bf16* p_hhi   = symaddrb(hid_hi);  bf16* p_hlo   = symaddrb(hid_lo);
    bf16* p_dhi   = symaddrb(dqk_hi);  bf16* p_dlo   = symaddrb(dqk_lo);
    bf16* p_phi   = symaddrb(pat_hi);  bf16* p_plo   = symaddrb(pat_lo);
    bf16* p_ench  = symaddrb(w_encT_hi); bf16* p_encl = symaddrb(w_encT_lo);
    bf16* p_dech  = symaddrb(w_decT_hi); bf16* p_decl = symaddrb(w_decT_lo);
    bf16* p_qfh   = symaddrb(w_qkfT_hi); bf16* p_qfl  = symaddrb(w_qkfT_lo);
    bf16* p_qbh   = symaddrb(w_qkbT_hi); bf16* p_qbl  = symaddrb(w_qkbT_lo);
    bf16* p_xth   = symaddrb(w_xiT_hi);  bf16* p_xtl  = symaddrb(w_xiT_lo);
    bf16* p_xih   = symaddrb(w_xi_hi);   bf16* p_xil  = symaddrb(w_xi_lo);

    cudaFuncSetAttribute(mma_gemm_k<0>, cudaFuncAttributeMaxDynamicSharedMemorySize, GEMM_SMEM);
    cudaFuncSetAttribute(mma_gemm_k<1>, cudaFuncAttributeMaxDynamicSharedMemorySize, GEMM_SMEM);
    cudaFuncSetAttribute(mma_gemm_k<2>, cudaFuncAttributeMaxDynamicSharedMemorySize, GEMM_SMEM);
    cudaFuncSetAttribute(mma_gemm_k<3>, cudaFuncAttributeMaxDynamicSharedMemorySize, GEMM_SMEM);

    const int MROWS = BB*NT;   // 3152
    const int PROWS = BB*NP;   // 3136

    // weight prep
    split_transpose_k<<<(DD*DD + 255)/256, 256>>>(enc_W, p_ench, p_encl, DD, DD);
    split_transpose_k<<<(DD*DD + 255)/256, 256>>>(dec_W, p_dech, p_decl, DD, DD);
    split_transpose_k<<<(DD*MH + 255)/256, 256>>>(Xi, p_xth, p_xtl, DD, MH);
    split_k<<<(DD*MH + 255)/256, 256>>>(Xi, p_xih, p_xil, DD*MH);
    prep_qk_k<<<(2*DD*DD + 255)/256, 256>>>(Wq, Wk);

    // encode
    patchify_k<<<(BB*NP*DD + 255)/256, 256>>>(img);
    mma_gemm_k<1><<<dim3(6,25), 256, GEMM_SMEM>>>(p_phi, p_plo, p_ench, p_encl,
        enc_b, p_tok, nullptr, nullptr, PROWS, DD, DD, DD, DD, DD);
    assemble_k<<<BB, 256>>>(mask, cls, mtok, pos);

    // 12 energy-descent steps
    for (int it = 0; it < 12; it++){
        lnorm_k<<<MROWS, 256>>>(p_x, p_ghi, p_glo, gamma, delta, 0);
        // qk = g @ [Wq|Wk]   (M=3152, N=1536, K=768)
        mma_gemm_k<0><<<dim3(12,25), 256, GEMM_SMEM>>>(p_ghi, p_glo, p_qfh, p_qfl,
            nullptr, p_qk, nullptr, nullptr, MROWS, 2*DD, DD, DD, DD, 2*DD);
        // hid = relu(g @ Xi) (N=3072) -> split bf16
        mma_gemm_k<2><<<dim3(24,25), 256, GEMM_SMEM>>>(p_ghi, p_glo, p_xth, p_xtl,
            nullptr, nullptr, p_hhi, p_hlo, MROWS, MH, DD, DD, DD, MH);
        // attention
        attn_scores_k<<<dim3(7,7,BB*NH), 256>>>();
        softmax_k<<<BB*NH*NT, 256>>>();
        pv_k<false><<<dim3(7,BB*NH), 256>>>();   // dq = P @ K
        pv_k<true ><<<dim3(7,BB*NH), 256>>>();   // dk = P^T @ Q
        // x += ALPHA * [dq|dk] @ [Wq;Wk]^T   (K=1536)
        mma_gemm_k<3><<<dim3(6,25), 256, GEMM_SMEM>>>(p_dhi, p_dlo, p_qbh, p_qbl,
            nullptr, p_x, nullptr, nullptr, MROWS, DD, 2*DD, 2*DD, 2*DD, DD);
        // x += ALPHA * hid @ Xi^T            (K=3072)
        mma_gemm_k<3><<<dim3(6,25), 256, GEMM_SMEM>>>(p_hhi, p_hlo, p_xih, p_xil,
            nullptr, p_x, nullptr, nullptr, MROWS, DD, MH, MH, MH, DD);
    }

    // decode
    lnorm_k<<<PROWS, 256>>>(p_x, p_phi, p_plo, gamma, delta, 1);
    mma_gemm_k<1><<<dim3(6,25), 256, GEMM_SMEM>>>(p_phi, p_plo, p_dech, p_decl,
        dec_b, p_tok, nullptr, nullptr, PROWS, DD, DD, DD, DD, DD);
    unpatchify_k<<<(BB*3*224*224 + 255)/256, 256>>>(p_tok, out);
}

// round 4
// speedup vs baseline: 4.9977x; 1.5428x over previous
#include <cuda_runtime.h>
#include <cuda_bf16.h>
#include <math.h>
#include <stdint.h>

#define BB   16
#define NP   196
#define NT   197
#define DD   768
#define NH   12
#define YY   64
#define MH   3072
#define NMASK 100
#define ALPHA 0.1f
#define BETA  0.125f
#define EPSLN 1e-5f

typedef __nv_bfloat16 bf16;

// ------------------------- scratch (static device memory) -------------------------
__device__ float d_x   [BB*NT*DD];
__device__ float d_tok [BB*NP*DD];

__device__ bf16 g_hi [BB*NT*DD],      g_lo [BB*NT*DD];
__device__ bf16 hid_hi[BB*NT*MH],     hid_lo[BB*NT*MH];
__device__ bf16 dqk_hi[BB*NT*2*DD],   dqk_lo[BB*NT*2*DD];
__device__ bf16 pat_hi[BB*NP*DD],     pat_lo[BB*NP*DD];
__device__ bf16 qk_hi [BB*NT*2*DD],   qk_lo [BB*NT*2*DD];   // q cols 0..767, k cols 768..1535

#define NBH   (BB*NH)          // 192
#define PQ    208              // padded token rows
#define PC    256              // padded token cols
__device__ bf16 P_hi [NBH*PQ*PC], P_lo [NBH*PQ*PC];   // P[bh][q][kv]
__device__ bf16 PT_hi[NBH*PQ*PC], PT_lo[NBH*PQ*PC];   // P^T[bh][kv][q]

__device__ bf16 w_encT_hi[DD*DD],     w_encT_lo[DD*DD];
__device__ bf16 w_decT_hi[DD*DD],     w_decT_lo[DD*DD];
__device__ bf16 w_qkfT_hi[2*DD*DD],   w_qkfT_lo[2*DD*DD];
__device__ bf16 w_qkbT_hi[2*DD*DD],   w_qkbT_lo[2*DD*DD];
__device__ bf16 w_xiT_hi [MH*DD],     w_xiT_lo [MH*DD];
__device__ bf16 w_xi_hi  [DD*MH],     w_xi_lo  [DD*MH];

// ------------------------- helpers -------------------------
__device__ __forceinline__ void split2(float v, bf16& h, bf16& l){
    h = __float2bfloat16(v);
    l = __float2bfloat16(v - __bfloat162float(h));
}
__device__ __forceinline__ void cp16(uint32_t saddr, const bf16* g, uint32_t sz){
    uint64_t ga = __cvta_generic_to_global(g);
    asm volatile("cp.async.cg.shared.global [%0], [%1], 16, %2;"
                 :: "r"(saddr), "l"(ga), "r"(sz) : "memory");
}
__device__ __forceinline__ void cp_commit(){ asm volatile("cp.async.commit_group;" ::: "memory"); }
template<int N>
__device__ __forceinline__ void cp_wait(){ asm volatile("cp.async.wait_group %0;" :: "n"(N) : "memory"); }

__device__ __forceinline__ void ldsm4(uint32_t* r, uint32_t a){
    asm volatile("ldmatrix.sync.aligned.m8n8.x4.shared.b16 {%0,%1,%2,%3}, [%4];"
                 : "=r"(r[0]), "=r"(r[1]), "=r"(r[2]), "=r"(r[3]) : "r"(a));
}
__device__ __forceinline__ void ldsm2(uint32_t* r, uint32_t a){
    asm volatile("ldmatrix.sync.aligned.m8n8.x2.shared.b16 {%0,%1}, [%2];"
                 : "=r"(r[0]), "=r"(r[1]) : "r"(a));
}
__device__ __forceinline__ void ldsm2t(uint32_t* r, uint32_t a){
    asm volatile("ldmatrix.sync.aligned.m8n8.x2.trans.shared.b16 {%0,%1}, [%2];"
                 : "=r"(r[0]), "=r"(r[1]) : "r"(a));
}
__device__ __forceinline__ void mma16816(float* c, const uint32_t* a, const uint32_t* b){
    asm volatile("mma.sync.aligned.m16n8k16.row.col.f32.bf16.bf16.f32 "
                 "{%0,%1,%2,%3}, {%4,%5,%6,%7}, {%8,%9}, {%0,%1,%2,%3};"
                 : "+f"(c[0]), "+f"(c[1]), "+f"(c[2]), "+f"(c[3])
                 : "r"(a[0]), "r"(a[1]), "r"(a[2]), "r"(a[3]), "r"(b[0]), "r"(b[1]));
}

// ------------------------- reductions -------------------------
__device__ __forceinline__ float bsum(float v){
    __shared__ float sh[32];
    int lane = threadIdx.x & 31, w = threadIdx.x >> 5;
    #pragma unroll
    for (int o = 16; o; o >>= 1) v += __shfl_xor_sync(0xffffffffu, v, o);
    __syncthreads();
    if (lane == 0) sh[w] = v;
    __syncthreads();
    float r = (lane < (int)(blockDim.x >> 5)) ? sh[lane] : 0.f;
    #pragma unroll
    for (int o = 16; o; o >>= 1) r += __shfl_xor_sync(0xffffffffu, r, o);
    return r;
}

// ------------------------- weight prep -------------------------
__global__ __launch_bounds__(256) void split_transpose_k(const float* __restrict__ W,
                                                         bf16* __restrict__ hi,
                                                         bf16* __restrict__ lo,
                                                         int R, int C){
    int o = blockIdx.x*256 + threadIdx.x;
    if (o >= R*C) return;
    int c = o / R, r = o - c*R;
    bf16 h, l; split2(W[(size_t)r*C + c], h, l);
    hi[o] = h; lo[o] = l;
}
__global__ __launch_bounds__(256) void split_k(const float* __restrict__ W,
                                               bf16* __restrict__ hi,
                                               bf16* __restrict__ lo, int n){
    int o = blockIdx.x*256 + threadIdx.x;
    if (o >= n) return;
    bf16 h, l; split2(W[o], h, l);
    hi[o] = h; lo[o] = l;
}
__global__ __launch_bounds__(256) void prep_qk_k(const float* __restrict__ Wq,
                                                 const float* __restrict__ Wk){
    int o = blockIdx.x*256 + threadIdx.x;
    if (o >= 2*DD*DD) return;
    int j = o / DD, d = o - j*DD;
    int jj = (j < DD) ? j : j - DD;
    int h = jj >> 6, y = jj & 63;
    const float* W = (j < DD) ? Wq : Wk;
    float v = W[(size_t)h*DD*YY + (size_t)d*YY + y];
    bf16 vh, vl; split2(v, vh, vl);
    w_qkfT_hi[(size_t)j*DD + d]   = vh;  w_qkfT_lo[(size_t)j*DD + d]   = vl;
    w_qkbT_hi[(size_t)d*2*DD + j] = vh;  w_qkbT_lo[(size_t)d*2*DD + j] = vl;
}

// ------------------------- patchify / unpatchify -------------------------
__global__ __launch_bounds__(256) void patchify_k(const float* __restrict__ img){
    int idx = blockIdx.x*256 + threadIdx.x;
    if (idx >= BB*NP*DD) return;
    int e  = idx % DD;
    int n  = (idx / DD) % NP;
    int b  = idx / (DD*NP);
    int c  = e >> 8, ph = (e >> 4) & 15, pw = e & 15;
    int kh = n / 14, kw = n % 14;
    float v = img[((b*3 + c)*224 + kh*16 + ph)*224 + kw*16 + pw];
    bf16 h, l; split2(v, h, l);
    pat_hi[idx] = h; pat_lo[idx] = l;
}
__global__ __launch_bounds__(256) void unpatchify_k(const float* __restrict__ dec,
                                                    float* __restrict__ out){
    int idx = blockIdx.x*256 + threadIdx.x;
    if (idx >= BB*3*224*224) return;
    int ww = idx % 224;
    int hh = (idx / 224) % 224;
    int c  = (idx / (224*224)) % 3;
    int b  = idx / (3*224*224);
    int kh = hh >> 4, ph = hh & 15, kw = ww >> 4, pw = ww & 15;
    int n = kh*14 + kw;
    int e = (c << 8) + (ph << 4) + pw;
    out[idx] = dec[(size_t)(b*NP + n)*DD + e];
}

// ------------------------- masking + token assembly -------------------------
__global__ __launch_bounds__(256) void assemble_k(const int* __restrict__ mask,
                                                  const float* __restrict__ cls,
                                                  const float* __restrict__ mtok,
                                                  const float* __restrict__ pos){
    int b = blockIdx.x;
    __shared__ unsigned char flag[NP];
    int tid = threadIdx.x;
    for (int i = tid; i < NP; i += 256) flag[i] = 0;
    __syncthreads();
    if (tid == 0){
        int cnt = 0;
        const int* mrow = mask + b*NP;
        for (int i = 0; i < NP; i++)
            if (mrow[i] == 1 && cnt < NMASK){ flag[i] = 1; cnt++; }
        if (cnt < NMASK) flag[0] = 1;
    }
    __syncthreads();
    float* xb = d_x + (size_t)b*NT*DD;
    for (int d = tid; d < DD; d += 256) xb[d] = cls[d] + pos[d];
    for (int n = 0; n < NP; n++){
        const float* src = flag[n] ? mtok : (d_tok + ((size_t)b*NP + n)*DD);
        for (int d = tid; d < DD; d += 256)
            xb[(1+n)*DD + d] = src[d] + pos[(1+n)*DD + d];
    }
}

// ------------------------- layernorm (emits bf16 hi/lo) -------------------------
__global__ __launch_bounds__(256) void lnorm_k(const float* __restrict__ x,
                                               bf16* __restrict__ ghi,
                                               bf16* __restrict__ glo,
                                               const float* __restrict__ gamma,
                                               const float* __restrict__ delta,
                                               int skipcls){
    int row = blockIdx.x;
    int srow = row;
    if (skipcls){ int b = row / NP; srow = b*NT + 1 + (row - b*NP); }
    const float* xr = x + (size_t)srow*DD;
    int tid = threadIdx.x;
    float v0 = xr[tid], v1 = xr[tid+256], v2 = xr[tid+512];
    float s = bsum(v0 + v1 + v2);
    float mean = s * (1.f/768.f);
    float e0 = v0 - mean, e1 = v1 - mean, e2 = v2 - mean;
    float s2 = bsum(e0*e0 + e1*e1 + e2*e2);
    float rinv = rsqrtf(s2 * (1.f/768.f) + EPSLN);
    float gm = gamma[0];
    float o0 = gm*e0*rinv + delta[tid];
    float o1 = gm*e1*rinv + delta[tid+256];
    float o2 = gm*e2*rinv + delta[tid+512];
    bf16* gh = ghi + (size_t)row*DD;
    bf16* gl = glo + (size_t)row*DD;
    bf16 h, l;
    split2(o0, h, l); gh[tid]     = h; gl[tid]     = l;
    split2(o1, h, l); gh[tid+256] = h; gl[tid+256] = l;
    split2(o2, h, l); gh[tid+512] = h; gl[tid+512] = l;
}

// ------------------------- mma.sync split-bf16 GEMM -------------------------
// EPI: 0 = fp32, 1 = fp32+bias, 2 = relu+split bf16, 3 = C += ALPHA*acc, 4 = split bf16
#define TILE_B   18432
#define STAGE_B  (4*TILE_B)
#define GEMM_SMEM (2*STAGE_B)

template<int EPI>
__global__ __launch_bounds__(256) void mma_gemm_k(
        const bf16* __restrict__ Ahi, const bf16* __restrict__ Alo,
        const bf16* __restrict__ Bhi, const bf16* __restrict__ Blo,
        const float* __restrict__ bias, float* __restrict__ C,
        bf16* __restrict__ Chi, bf16* __restrict__ Clo,
        int M, int N, int K, int lda, int ldb, int ldc){
    extern __shared__ char smem[];
    uint32_t sb = (uint32_t)__cvta_generic_to_shared(smem);
    int tid = threadIdx.x;
    int lane = tid & 31, wid = tid >> 5;
    int wm = wid >> 2, wn = wid & 3;
    int m0 = blockIdx.y * 128, n0 = blockIdx.x * 128;
    int mrows = M - m0; if (mrows > 128) mrows = 128;
    int nst = K >> 6;

    float acc[4][4][4];
    #pragma unroll
    for (int a = 0; a < 4; a++)
        #pragma unroll
        for (int b = 0; b < 4; b++)
            #pragma unroll
            for (int c = 0; c < 4; c++) acc[a][b][c] = 0.f;

    auto load_stage = [&](int s){
        uint32_t base = sb + (s & 1) * STAGE_B;
        int k0 = s << 6;
        #pragma unroll
        for (int it = 0; it < 4; it++){
            int c = (it << 8) + tid;
            int r = c >> 3;
            int kq = (c & 7) << 3;
            uint32_t soff = r*144 + (kq << 1);
            uint32_t szA = (r < mrows) ? 16u : 0u;
            int ra = (r < mrows) ? r : 0;
            cp16(base + soff,            Ahi + (size_t)(m0+ra)*lda + k0 + kq, szA);
            cp16(base + TILE_B + soff,   Alo + (size_t)(m0+ra)*lda + k0 + kq, szA);
            cp16(base + 2*TILE_B + soff, Bhi + (size_t)(n0+r)*ldb + k0 + kq, 16u);
            cp16(base + 3*TILE_B + soff, Blo + (size_t)(n0+r)*ldb + k0 + kq, 16u);
        }
        cp_commit();
    };

    auto compute_stage = [&](int s){
        uint32_t base = sb + (s & 1) * STAGE_B;
        uint32_t aRow = (uint32_t)(wm*64 + (lane & 15))*144;
        uint32_t aHi8 = (uint32_t)((lane >> 4) << 3);
        uint32_t bRow = (uint32_t)(wn*32 + (lane & 7))*144;
        uint32_t bHi8 = (uint32_t)(((lane >> 3) & 1) << 3);
        #pragma unroll
        for (int kk = 0; kk < 64; kk += 16){
            uint32_t ah[4][4], al[4][4], bh[4][2], bl[4][2];
            uint32_t aoff = base + aRow + ((kk + aHi8) << 1);
            uint32_t boff = base + 2*TILE_B + bRow + ((kk + bHi8) << 1);
            #pragma unroll
            for (int mt = 0; mt < 4; mt++){
                ldsm4(ah[mt], aoff + mt*(16*144));
                ldsm4(al[mt], aoff + TILE_B + mt*(16*144));
            }
            #pragma unroll
            for (int nt = 0; nt < 4; nt++){
                ldsm2(bh[nt], boff + nt*(8*144));
                ldsm2(bl[nt], boff + TILE_B + nt*(8*144));
            }
            #pragma unroll
            for (int mt = 0; mt < 4; mt++)
                #pragma unroll
                for (int nt = 0; nt < 4; nt++){
                    mma16816(acc[mt][nt], ah[mt], bh[nt]);
                    mma16816(acc[mt][nt], ah[mt], bl[nt]);
                    mma16816(acc[mt][nt], al[mt], bh[nt]);
                }
        }
    };

    load_stage(0);
    for (int s = 0; s < nst; s++){
        if (s + 1 < nst){
            load_stage(s + 1);
            cp_wait<1>();
        } else {
            cp_wait<0>();
        }
        __syncthreads();
        compute_stage(s);
        __syncthreads();
    }

    int g = lane >> 2;
    int t2 = (lane & 3) << 1;
    #pragma unroll
    for (int mt = 0; mt < 4; mt++){
        int r0 = m0 + wm*64 + mt*16 + g;
        #pragma unroll
        for (int half = 0; half < 2; half++){
            int row = r0 + half*8;
            if (row >= M) continue;
            #pragma unroll
            for (int nt = 0; nt < 4; nt++){
                int col = n0 + wn*32 + nt*8 + t2;
                float v0 = acc[mt][nt][half*2];
                float v1 = acc[mt][nt][half*2 + 1];
                if (EPI == 0 || EPI == 1){
                    if (EPI == 1){ v0 += bias[col]; v1 += bias[col+1]; }
                    *(float2*)(C + (size_t)row*ldc + col) = make_float2(v0, v1);
                } else if (EPI == 2 || EPI == 4){
                    if (EPI == 2){ v0 = fmaxf(v0, 0.f); v1 = fmaxf(v1, 0.f); }
                    bf16 h0, l0, h1, l1;
                    split2(v0, h0, l0); split2(v1, h1, l1);
                    *(__nv_bfloat162*)(Chi + (size_t)row*ldc + col) = __halves2bfloat162(h0, h1);
                    *(__nv_bfloat162*)(Clo + (size_t)row*ldc + col) = __halves2bfloat162(l0, l1);
                } else {
                    float2* cp = (float2*)(C + (size_t)row*ldc + col);
                    float2 o = *cp;
                    o.x += ALPHA * v0;
                    o.y += ALPHA * v1;
                    *cp = o;
                }
            }
        }
    }
}

// ------------------------- fused attention A: S, softmax, P/PT, dq -------------------------
// one CTA per (bh, 64-q-row tile); 256 threads, 8 warps
#define AT_KHI 0
#define AT_KLO 29952
#define AT_QHI 59904
#define AT_QLO 69120
#define AT_S   78336
#define AT_PHI 132352
#define AT_PLO 160000
#define AT_SMEM 187648

__global__ __launch_bounds__(256) void attnA_k(){
    extern __shared__ char sm[];
    uint32_t sb = (uint32_t)__cvta_generic_to_shared(sm);
    int tid = threadIdx.x, lane = tid & 31, wid = tid >> 5;
    int bh = blockIdx.y, b = bh / NH, h = bh - b*NH;
    int q0 = blockIdx.x * 64;

    bf16* Khi = (bf16*)(sm + AT_KHI);
    bf16* Klo = (bf16*)(sm + AT_KLO);
    bf16* Qhi = (bf16*)(sm + AT_QHI);
    bf16* Qlo = (bf16*)(sm + AT_QLO);
    float* Ssm = (float*)(sm + AT_S);
    bf16* Phi = (bf16*)(sm + AT_PHI);
    bf16* Plo = (bf16*)(sm + AT_PLO);

    const uint4 z4 = make_uint4(0u,0u,0u,0u);
    // K: 208 rows x 64 (zero-padded)
    for (int i = tid; i < 208*8; i += 256){
        int r = i >> 3, c8 = (i & 7) << 3;
        uint4 vh = z4, vl = z4;
        if (r < NT){
            size_t go = (size_t)(b*NT + r)*1536 + 768 + h*64 + c8;
            vh = *(const uint4*)(qk_hi + go);
            vl = *(const uint4*)(qk_lo + go);
        }
        *(uint4*)(Khi + r*72 + c8) = vh;
        *(uint4*)(Klo + r*72 + c8) = vl;
    }
    // Q: 64 rows
    for (int i = tid; i < 64*8; i += 256){
        int r = i >> 3, c8 = (i & 7) << 3;
        uint4 vh = z4, vl = z4;
        if (q0 + r < NT){
            size_t go = (size_t)(b*NT + q0 + r)*1536 + h*64 + c8;
            vh = *(const uint4*)(qk_hi + go);
            vl = *(const uint4*)(qk_lo + go);
        }
        *(uint4*)(Qhi + r*72 + c8) = vh;
        *(uint4*)(Qlo + r*72 + c8) = vl;
    }
    __syncthreads();

    uint32_t uK  = sb + AT_KHI, uKl = sb + AT_KLO;
    uint32_t uQ  = sb + AT_QHI, uQl = sb + AT_QLO;

    // ---- S = BETA * Q K^T ----  warps: wm(2) x wn(4); warp tile 32 x 64
    {
        int wm = wid & 1, wn = wid >> 1;
        float acc[2][8][4];
        #pragma unroll
        for (int a = 0; a < 2; a++)
            #pragma unroll
            for (int c = 0; c < 8; c++)
                #pragma unroll
                for (int d = 0; d < 4; d++) acc[a][c][d] = 0.f;
        #pragma unroll
        for (int kk = 0; kk < 64; kk += 16){
            uint32_t ah[2][4], al[2][4], bhf[8][2], blf[8][2];
            uint32_t acb = (uint32_t)((kk + ((lane >> 4) << 3)) << 1);
            #pragma unroll
            for (int mt = 0; mt < 2; mt++){
                uint32_t ro = (uint32_t)(wm*32 + mt*16 + (lane & 15))*144;
                ldsm4(ah[mt], uQ  + ro + acb);
                ldsm4(al[mt], uQl + ro + acb);
            }
            uint32_t bcb = (uint32_t)((kk + (((lane >> 3) & 1) << 3)) << 1);
            #pragma unroll
            for (int nt = 0; nt < 8; nt++){
                uint32_t ro = (uint32_t)(wn*64 + nt*8 + (lane & 7))*144;
                ldsm2(bhf[nt], uK  + ro + bcb);
                ldsm2(blf[nt], uKl + ro + bcb);
            }
            #pragma unroll
            for (int mt = 0; mt < 2; mt++)
                #pragma unroll
                for (int nt = 0; nt < 8; nt++){
                    mma16816(acc[mt][nt], ah[mt], bhf[nt]);
                    mma16816(acc[mt][nt], ah[mt], blf[nt]);
                    mma16816(acc[mt][nt], al[mt], bhf[nt]);
                }
        }
        // store S
        #pragma unroll
        for (int mt = 0; mt < 2; mt++){
            int r = wm*32 + mt*16 + (lane >> 2);
            #pragma unroll
            for (int nt = 0; nt < 8; nt++){
                int c = wn*64 + nt*8 + ((lane & 3) << 1);
                if (c < 208){
                    Ssm[r*211 + c]       = BETA*acc[mt][nt][0];
                    Ssm[r*211 + c + 1]   = BETA*acc[mt][nt][1];
                    Ssm[(r+8)*211 + c]   = BETA*acc[mt][nt][2];
                    Ssm[(r+8)*211 + c+1] = BETA*acc[mt][nt][3];
                }
            }
        }
    }
    __syncthreads();

    // ---- softmax: warp w handles rows w*8..w*8+7 ----
    for (int rr = 0; rr < 8; rr++){
        int r = wid*8 + rr;
        float mx = -3.0e38f;
        for (int c = lane; c < NT; c += 32) mx = fmaxf(mx, Ssm[r*211 + c]);
        #pragma unroll
        for (int o = 16; o; o >>= 1) mx = fmaxf(mx, __shfl_xor_sync(0xffffffffu, mx, o));
        float s = 0.f;
        for (int c = lane; c < NT; c += 32){
            float e = __expf(Ssm[r*211 + c] - mx);
            Ssm[r*211 + c] = e;
            s += e;
        }
        #pragma unroll
        for (int o = 16; o; o >>= 1) s += __shfl_xor_sync(0xffffffffu, s, o);
        float inv = 1.f / s;
        for (int c = lane; c < NT; c += 32) Ssm[r*211 + c] *= inv;
    }
    __syncthreads();

    // ---- P smem (bf16 split, zero pad cols>=197), P & PT global ----
    for (int idx = tid; idx < 64*208; idx += 256){
        int r = idx / 208, c = idx - r*208;
        float v = (c < NT) ? Ssm[r*211 + c] : 0.f;
        bf16 hh, ll; split2(v, hh, ll);
        Phi[r*216 + c] = hh; Plo[r*216 + c] = ll;
    }
    for (int idx = tid; idx < 64*128; idx += 256){
        int r = idx >> 7, cp = (idx & 127) << 1;
        int q = q0 + r;
        if (q < PQ){
            bool vr = (q < NT);
            float v0 = (vr && cp < NT)     ? Ssm[r*211 + cp]     : 0.f;
            float v1 = (vr && cp + 1 < NT) ? Ssm[r*211 + cp + 1] : 0.f;
            bf16 h0, l0, h1, l1; split2(v0, h0, l0); split2(v1, h1, l1);
            size_t o = ((size_t)bh*PQ + q)*PC + cp;
            *(__nv_bfloat162*)(P_hi + o) = __halves2bfloat162(h0, h1);
            *(__nv_bfloat162*)(P_lo + o) = __halves2bfloat162(l0, l1);
        }
    }
    for (int idx = tid; idx < 208*64; idx += 256){
        int c = idx >> 6, rr = idx & 63;
        int q = q0 + rr;
        float v = (c < NT && q < NT) ? Ssm[rr*211 + c] : 0.f;
        bf16 hh, ll; split2(v, hh, ll);
        size_t o = ((size_t)bh*PQ + c)*PC + q;
        PT_hi[o] = hh; PT_lo[o] = ll;
    }
    __syncthreads();

    // ---- dq = P @ K ----  warps: wm2(2) x wn2(4); warp tile 32 x 16
    {
        int wm2 = wid & 1, wn2 = wid >> 1;
        uint32_t uP = sb + AT_PHI, uPl = sb + AT_PLO;
        float acc[2][2][4];
        #pragma unroll
        for (int a = 0; a < 2; a++)
            #pragma unroll
            for (int c = 0; c < 2; c++)
                #pragma unroll
                for (int d = 0; d < 4; d++) acc[a][c][d] = 0.f;
        for (int kk = 0; kk < 208; kk += 16){
            uint32_t ah[2][4], al[2][4], bhf[2][2], blf[2][2];
            uint32_t acb = (uint32_t)((kk + ((lane >> 4) << 3)) << 1);
            #pragma unroll
            for (int mt = 0; mt < 2; mt++){
                uint32_t ro = (uint32_t)(wm2*32 + mt*16 + (lane & 15))*432;
                ldsm4(ah[mt], uP  + ro + acb);
                ldsm4(al[mt], uPl + ro + acb);
            }
            uint32_t brow = (uint32_t)(kk + (lane & 15))*144;
            #pragma unroll
            for (int nt = 0; nt < 2; nt++){
                uint32_t co = (uint32_t)((wn2*16 + nt*8) << 1);
                ldsm2t(bhf[nt], uK  + brow + co);
                ldsm2t(blf[nt], uKl + brow + co);
            }
            #pragma unroll
            for (int mt = 0; mt < 2; mt++)
                #pragma unroll
                for (int nt = 0; nt < 2; nt++){
                    mma16816(acc[mt][nt], ah[mt], bhf[nt]);
                    mma16816(acc[mt][nt], ah[mt], blf[nt]);
                    mma16816(acc[mt][nt], al[mt], bhf[nt]);
                }
        }
        #pragma unroll
        for (int mt = 0; mt < 2; mt++){
            #pragma unroll
            for (int half = 0; half < 2; half++){
                int q = q0 + wm2*32 + mt*16 + (lane >> 2) + half*8;
                if (q >= NT) continue;
                #pragma unroll
                for (int nt = 0; nt < 2; nt++){
                    int cc = wn2*16 + nt*8 + ((lane & 3) << 1);
                    bf16 h0, l0, h1, l1;
                    split2(acc[mt][nt][half*2],     h0, l0);
                    split2(acc[mt][nt][half*2 + 1], h1, l1);
                    size_t o = (size_t)(b*NT + q)*1536 + h*64 + cc;
                    *(__nv_bfloat162*)(dqk_hi + o) = __halves2bfloat162(h0, h1);
                    *(__nv_bfloat162*)(dqk_lo + o) = __halves2bfloat162(l0, l1);
                }
            }
        }
    }
}

// ------------------------- attention B: dk = P^T @ Q -------------------------
__global__ __launch_bounds__(256) void attnB_k(){
    __shared__ bf16 Ah[64*72], Al[64*72], Qh[64*72], Ql[64*72];
    uint32_t uA  = (uint32_t)__cvta_generic_to_shared(Ah);
    uint32_t uAl = (uint32_t)__cvta_generic_to_shared(Al);
    uint32_t uQ  = (uint32_t)__cvta_generic_to_shared(Qh);
    uint32_t uQl = (uint32_t)__cvta_generic_to_shared(Ql);
    int tid = threadIdx.x, lane = tid & 31, wid = tid >> 5;
    int bh = blockIdx.y, b = bh / NH, h = bh - b*NH;
    int kv0 = blockIdx.x * 64;
    int wm2 = wid & 1, wn2 = wid >> 1;
    const uint4 z4 = make_uint4(0u,0u,0u,0u);

    float acc[2][2][4];
    #pragma unroll
    for (int a = 0; a < 2; a++)
        #pragma unroll
        for (int c = 0; c < 2; c++)
            #pragma unroll
            for (int d = 0; d < 4; d++) acc[a][c][d] = 0.f;

    for (int qc = 0; qc < 256; qc += 64){
        __syncthreads();
        for (int i = tid; i < 64*8; i += 256){
            int r = i >> 3, c8 = (i & 7) << 3;
            int kvr = kv0 + r;
            uint4 vh = z4, vl = z4;
            if (kvr < PQ){
                size_t o = ((size_t)bh*PQ + kvr)*PC + qc + c8;
                vh = *(const uint4*)(PT_hi + o);
                vl = *(const uint4*)(PT_lo + o);
            }
            *(uint4*)(Ah + r*72 + c8) = vh;
            *(uint4*)(Al + r*72 + c8) = vl;
        }
        for (int i = tid; i < 64*8; i += 256){
            int r = i >> 3, c8 = (i & 7) << 3;
            uint4 vh = z4, vl = z4;
            if (qc + r < NT){
                size_t o = (size_t)(b*NT + qc + r)*1536 + h*64 + c8;
                vh = *(const uint4*)(qk_hi + o);
                vl = *(const uint4*)(qk_lo + o);
            }
            *(uint4*)(Qh + r*72 + c8) = vh;
            *(uint4*)(Ql + r*72 + c8) = vl;
        }
        __syncthreads();
        #pragma unroll
        for (int kk = 0; kk < 64; kk += 16){
            uint32_t ah[2][4], al2[2][4], bhf[2][2], blf[2][2];
            uint32_t acb = (uint32_t)((kk + ((lane >> 4) << 3)) << 1);
            #pragma unroll
            for (int mt = 0; mt < 2; mt++){
                uint32_t ro = (uint32_t)(wm2*32 + mt*16 + (lane & 15))*144;
                ldsm4(ah[mt],  uA  + ro + acb);
                ldsm4(al2[mt], uAl + ro + acb);
            }
            uint32_t brow = (uint32_t)(kk + (lane & 15))*144;
            #pragma unroll
            for (int nt = 0; nt < 2; nt++){
                uint32_t co = (uint32_t)((wn2*16 + nt*8) << 1);
                ldsm2t(bhf[nt], uQ  + brow + co);
                ldsm2t(blf[nt], uQl + brow + co);
            }
            #pragma unroll
            for (int mt = 0; mt < 2; mt++)
                #pragma unroll
                for (int nt = 0; nt < 2; nt++){
                    mma16816(acc[mt][nt], ah[mt],  bhf[nt]);
                    mma16816(acc[mt][nt], ah[mt],  blf[nt]);
                    mma16816(acc[mt][nt], al2[mt], bhf[nt]);
                }
        }
    }
    #pragma unroll
    for (int mt = 0; mt < 2; mt++){
        #pragma unroll
        for (int half = 0; half < 2; half++){
            int kv = kv0 + wm2*32 + mt*16 + (lane >> 2) + half*8;
            if (kv >= NT) continue;
            #pragma unroll
            for (int nt = 0; nt < 2; nt++){
                int cc = wn2*16 + nt*8 + ((lane & 3) << 1);
                bf16 h0, l0, h1, l1;
                split2(acc[mt][nt][half*2],     h0, l0);
                split2(acc[mt][nt][half*2 + 1], h1, l1);
                size_t o = (size_t)(b*NT + kv)*1536 + 768 + h*64 + cc;
                *(__nv_bfloat162*)(dqk_hi + o) = __halves2bfloat162(h0, h1);
                *(__nv_bfloat162*)(dqk_lo + o) = __halves2bfloat162(l0, l1);
            }
        }
    }
}

// ------------------------- host orchestration -------------------------
template<typename T>
static float* symaddrf(const T& s){ void* p = nullptr; cudaGetSymbolAddress(&p, s); return (float*)p; }
template<typename T>
static bf16* symaddrb(const T& s){ void* p = nullptr; cudaGetSymbolAddress(&p, s); return (bf16*)p; }

extern "C" void kernel_launch(void* const* d_in, const int* in_sizes, int n_in,
                              void* d_out, int out_size){
    const float* img   = (const float*)d_in[0];
    const int*   mask  = (const int*)  d_in[1];
    const float* enc_W = (const float*)d_in[2];
    const float* enc_b = (const float*)d_in[3];
    const float* dec_W = (const float*)d_in[4];
    const float* dec_b = (const float*)d_in[5];
    const float* cls   = (const float*)d_in[6];
    const float* mtok  = (const float*)d_in[7];
    const float* pos   = (const float*)d_in[8];
    const float* Wq    = (const float*)d_in[9];
    const float* Wk    = (const float*)d_in[10];
    const float* Xi    = (const float*)d_in[11];
    const float* gamma = (const float*)d_in[12];
    const float* delta = (const float*)d_in[13];
    float* out = (float*)d_out;

    float* p_x    = symaddrf(d_x);
    float* p_tok  = symaddrf(d_tok);
    bf16* p_ghi   = symaddrb(g_hi);    bf16* p_glo   = symaddrb(g_lo);
    bf16* p_hhi   = symaddrb(hid_hi);  bf16* p_hlo   = symaddrb(hid_lo);
    bf16* p_dhi   = symaddrb(dqk_hi);  bf16* p_dlo   = symaddrb(dqk_lo);
    bf16* p_phi   = symaddrb(pat_hi);  bf16* p_plo   = symaddrb(pat_lo);
    bf16* p_qkh   = symaddrb(qk_hi);   bf16* p_qkl   = symaddrb(qk_lo);
    bf16* p_ench  = symaddrb(w_encT_hi); bf16* p_encl = symaddrb(w_encT_lo);
    bf16* p_dech  = symaddrb(w_decT_hi); bf16* p_decl = symaddrb(w_decT_lo);
    bf16* p_qfh   = symaddrb(w_qkfT_hi); bf16* p_qfl  = symaddrb(w_qkfT_lo);
    bf16* p_qbh   = symaddrb(w_qkbT_hi); bf16* p_qbl  = symaddrb(w_qkbT_lo);
    bf16* p_xth   = symaddrb(w_xiT_hi);  bf16* p_xtl  = symaddrb(w_xiT_lo);
    bf16* p_xih   = symaddrb(w_xi_hi);   bf16* p_xil  = symaddrb(w_xi_lo);

    cudaFuncSetAttribute(mma_gemm_k<0>, cudaFuncAttributeMaxDynamicSharedMemorySize, GEMM_SMEM);
    cudaFuncSetAttribute(mma_gemm_k<1>, cudaFuncAttributeMaxDynamicSharedMemorySize, GEMM_SMEM);
    cudaFuncSetAttribute(mma_gemm_k<2>, cudaFuncAttributeMaxDynamicSharedMemorySize, GEMM_SMEM);
    cudaFuncSetAttribute(mma_gemm_k<3>, cudaFuncAttributeMaxDynamicSharedMemorySize, GEMM_SMEM);
    cudaFuncSetAttribute(mma_gemm_k<4>, cudaFuncAttributeMaxDynamicSharedMemorySize, GEMM_SMEM);
    cudaFuncSetAttribute(attnA_k, cudaFuncAttributeMaxDynamicSharedMemorySize, AT_SMEM);

    const int MROWS = BB*NT;   // 3152
    const int PROWS = BB*NP;   // 3136

    // launch order chosen so ncu (-s 5 -c 1) captures the encode GEMM
    patchify_k<<<(BB*NP*DD + 255)/256, 256>>>(img);                                   // 0
    split_transpose_k<<<(DD*DD + 255)/256, 256>>>(enc_W, p_ench, p_encl, DD, DD);     // 1
    split_transpose_k<<<(DD*DD + 255)/256, 256>>>(dec_W, p_dech, p_decl, DD, DD);     // 2
    split_transpose_k<<<(DD*MH + 255)/256, 256>>>(Xi, p_xth, p_xtl, DD, MH);          // 3
    split_k<<<(DD*MH + 255)/256, 256>>>(Xi, p_xih, p_xil, DD*MH);                     // 4
    mma_gemm_k<1><<<dim3(6,25), 256, GEMM_SMEM>>>(p_phi, p_plo, p_ench, p_encl,       // 5
        enc_b, p_tok, nullptr, nullptr, PROWS, DD, DD, DD, DD, DD);
    prep_qk_k<<<(2*DD*DD + 255)/256, 256>>>(Wq, Wk);                                  // 6
    assemble_k<<<BB, 256>>>(mask, cls, mtok, pos);                                    // 7

    for (int it = 0; it < 12; it++){
        lnorm_k<<<MROWS, 256>>>(p_x, p_ghi, p_glo, gamma, delta, 0);
        // qk = g @ [Wq|Wk] -> split bf16
        mma_gemm_k<4><<<dim3(12,25), 256, GEMM_SMEM>>>(p_ghi, p_glo, p_qfh, p_qfl,
            nullptr, nullptr, p_qkh, p_qkl, MROWS, 2*DD, DD, DD, DD, 2*DD);
        // hid = relu(g @ Xi) -> split bf16
        mma_gemm_k<2><<<dim3(24,25), 256, GEMM_SMEM>>>(p_ghi, p_glo, p_xth, p_xtl,
            nullptr, nullptr, p_hhi, p_hlo, MROWS, MH, DD, DD, DD, MH);
        // fused attention
        attnA_k<<<dim3(4, NBH), 256, AT_SMEM>>>();
        attnB_k<<<dim3(4, NBH), 256>>>();
        // x += ALPHA * [dq|dk] @ [Wq;Wk]^T
        mma_gemm_k<3><<<dim3(6,25), 256, GEMM_SMEM>>>(p_dhi, p_dlo, p_qbh, p_qbl,
            nullptr, p_x, nullptr, nullptr, MROWS, DD, 2*DD, 2*DD, 2*DD, DD);
        // x += ALPHA * hid @ Xi^T
        mma_gemm_k<3><<<dim3(6,25), 256, GEMM_SMEM>>>(p_hhi, p_hlo, p_xih, p_xil,
            nullptr, p_x, nullptr, nullptr, MROWS, DD, MH, MH, MH, DD);
    }

    lnorm_k<<<PROWS, 256>>>(p_x, p_phi, p_plo, gamma, delta, 1);
    mma_gemm_k<1><<<dim3(6,25), 256, GEMM_SMEM>>>(p_phi, p_plo, p_dech, p_decl,
        dec_b, p_tok, nullptr, nullptr, PROWS, DD, DD, DD, DD, DD);
    unpatchify_k<<<(BB*3*224*224 + 255)/256, 256>>>(p_tok, out);
}